// round 6
// baseline (speedup 1.0000x reference)
#include <cuda_runtime.h>
#include <cuda_bf16.h>

// Problem constants
#define N_NODES  50000
#define N_EDGES  1600000
#define E_TOT    (N_EDGES + N_NODES)   // with self loops
#define IN_C     256
#define HID_C    128
#define OUT_C    16
#define HEADS    8
#define C1       16                    // HID_C / HEADS
#define NEG_SLOPE 0.2f

// ---------------------------------------------------------------------------
// Scratch (device globals; allocation inside kernel_launch is forbidden)
// ---------------------------------------------------------------------------
__device__ float g_h1[(size_t)N_NODES * HID_C];     // layer1 transformed features
__device__ float g_asrc1[(size_t)N_NODES * HEADS];
__device__ float g_adst1[(size_t)N_NODES * HEADS];
__device__ float g_denom1[(size_t)N_NODES * HEADS];
__device__ float g_out1[(size_t)N_NODES * HID_C];   // layer1 aggregation -> relu -> h2
__device__ float g_h3[(size_t)N_NODES * OUT_C];     // layer2 transformed features
__device__ float g_asrc2[N_NODES];
__device__ float g_adst2[N_NODES];
__device__ float g_denom2[N_NODES];

// ---------------------------------------------------------------------------
// Zero-init: g_out1 (6.4M), g_denom1 (400K), g_denom2 (50K)
// ---------------------------------------------------------------------------
__global__ void zero_scratch_kernel() {
    int idx = blockIdx.x * blockDim.x + threadIdx.x;
    if (idx < N_NODES * HID_C)  g_out1[idx]   = 0.f;
    if (idx < N_NODES * HEADS)  g_denom1[idx] = 0.f;
    if (idx < N_NODES)          g_denom2[idx] = 0.f;
}

__global__ void zero_out_kernel(float* p, int n) {
    int idx = blockIdx.x * blockDim.x + threadIdx.x;
    if (idx < n) p[idx] = 0.f;
}

// ---------------------------------------------------------------------------
// GEMM1: C[50000,128] = A[50000,256] @ B[256,128]
// BM=128 BN=128 BK=8, 256 threads, 8x8 per thread
// ---------------------------------------------------------------------------
__global__ __launch_bounds__(256) void gemm1_kernel(
    const float* __restrict__ A, const float* __restrict__ B, float* __restrict__ C)
{
    __shared__ float As[8][128];
    __shared__ float Bs[8][128];

    const int tid = threadIdx.x;
    const int tx = tid % 16;        // col group
    const int ty = tid / 16;        // row group
    const int row0 = blockIdx.x * 128;

    const int aRow = tid >> 1;          // 0..127
    const int aCol = (tid & 1) * 4;     // 0 or 4
    const int bRow = tid >> 5;          // 0..7
    const int bCol = (tid & 31) * 4;    // 0..124

    float acc[8][8];
    #pragma unroll
    for (int i = 0; i < 8; i++)
        #pragma unroll
        for (int j = 0; j < 8; j++) acc[i][j] = 0.f;

    for (int kt = 0; kt < IN_C; kt += 8) {
        int gr = row0 + aRow;
        float4 av = (gr < N_NODES)
            ? *reinterpret_cast<const float4*>(A + (size_t)gr * IN_C + kt + aCol)
            : make_float4(0.f, 0.f, 0.f, 0.f);
        As[aCol + 0][aRow] = av.x;
        As[aCol + 1][aRow] = av.y;
        As[aCol + 2][aRow] = av.z;
        As[aCol + 3][aRow] = av.w;

        float4 bv = *reinterpret_cast<const float4*>(B + (size_t)(kt + bRow) * 128 + bCol);
        *reinterpret_cast<float4*>(&Bs[bRow][bCol]) = bv;

        __syncthreads();

        #pragma unroll
        for (int k = 0; k < 8; k++) {
            float ra[8], rb[8];
            #pragma unroll
            for (int i = 0; i < 8; i++) ra[i] = As[k][ty * 8 + i];
            #pragma unroll
            for (int j = 0; j < 8; j++) rb[j] = Bs[k][tx * 8 + j];
            #pragma unroll
            for (int i = 0; i < 8; i++)
                #pragma unroll
                for (int j = 0; j < 8; j++) acc[i][j] += ra[i] * rb[j];
        }
        __syncthreads();
    }

    #pragma unroll
    for (int i = 0; i < 8; i++) {
        int r = row0 + ty * 8 + i;
        if (r < N_NODES) {
            #pragma unroll
            for (int j = 0; j < 8; j += 4) {
                float4 v = make_float4(acc[i][j], acc[i][j+1], acc[i][j+2], acc[i][j+3]);
                *reinterpret_cast<float4*>(C + (size_t)r * 128 + tx * 8 + j) = v;
            }
        }
    }
}

// ---------------------------------------------------------------------------
// Attention dot products, layer 1: one thread per (node, head)
// ---------------------------------------------------------------------------
__global__ void attdot1_kernel(const float* __restrict__ att_src,
                               const float* __restrict__ att_dst)
{
    int idx = blockIdx.x * blockDim.x + threadIdx.x;  // n*8 + head
    if (idx >= N_NODES * HEADS) return;
    int head = idx & 7;
    const float* hp = g_h1 + (size_t)(idx >> 3) * HID_C + head * C1;
    const float* sp = att_src + head * C1;
    const float* dp = att_dst + head * C1;
    float ss = 0.f, dd = 0.f;
    #pragma unroll
    for (int c = 0; c < C1; c++) {
        float v = hp[c];
        ss += v * sp[c];
        dd += v * dp[c];
    }
    g_asrc1[idx] = ss;
    g_adst1[idx] = dd;
}

// ---------------------------------------------------------------------------
// Edge pass: softmax denominator, layer 1. Thread per (edge, head).
// NOTE: segment-max subtraction skipped — mathematically identical softmax,
// logits are small (|alpha| < ~5) so exp is safe in fp32.
// ---------------------------------------------------------------------------
__global__ void edge_denom1_kernel(const int* __restrict__ ei)
{
    long long idx = (long long)blockIdx.x * blockDim.x + threadIdx.x;
    if (idx >= (long long)E_TOT * HEADS) return;
    int e = (int)(idx >> 3);
    int h = (int)(idx & 7);
    int s, d;
    if (e < N_EDGES) { s = ei[e]; d = ei[N_EDGES + e]; }
    else             { s = d = e - N_EDGES; }
    float a = g_asrc1[s * HEADS + h] + g_adst1[d * HEADS + h];
    a = (a > 0.f) ? a : NEG_SLOPE * a;
    atomicAdd(&g_denom1[d * HEADS + h], __expf(a));
}

// ---------------------------------------------------------------------------
// Edge pass: weighted scatter, layer 1. One warp per edge; lane handles 4 ch.
// ---------------------------------------------------------------------------
__global__ void edge_scatter1_kernel(const int* __restrict__ ei)
{
    int warp = (blockIdx.x * blockDim.x + threadIdx.x) >> 5;
    int lane = threadIdx.x & 31;
    if (warp >= E_TOT) return;
    int s, d;
    if (warp < N_EDGES) { s = ei[warp]; d = ei[N_EDGES + warp]; }
    else                { s = d = warp - N_EDGES; }
    int head = lane >> 2;
    float a = g_asrc1[s * HEADS + head] + g_adst1[d * HEADS + head];
    a = (a > 0.f) ? a : NEG_SLOPE * a;
    float w = __expf(a) / g_denom1[d * HEADS + head];

    float4 hv = *reinterpret_cast<const float4*>(g_h1 + (size_t)s * HID_C + lane * 4);
    float4 m = make_float4(hv.x * w, hv.y * w, hv.z * w, hv.w * w);
    atomicAdd(reinterpret_cast<float4*>(g_out1 + (size_t)d * HID_C + lane * 4), m);
}

// ---------------------------------------------------------------------------
// Epilogue layer 1: bias + relu (in place; g_out1 becomes h2)
// ---------------------------------------------------------------------------
__global__ void relu_bias1_kernel(const float* __restrict__ bias1)
{
    int idx = blockIdx.x * blockDim.x + threadIdx.x;
    if (idx >= N_NODES * HID_C) return;
    float v = g_out1[idx] + bias1[idx & (HID_C - 1)];
    g_out1[idx] = (v > 0.f) ? v : 0.f;
}

// ---------------------------------------------------------------------------
// GEMM2: C[50000,16] = h2[50000,128] @ W2[128,16]
// block = 256 threads = 16 nodes x 16 outputs
// ---------------------------------------------------------------------------
__global__ __launch_bounds__(256) void gemm2_kernel(const float* __restrict__ W)
{
    __shared__ float Ws[128 * 16];
    __shared__ float Hs[16][128];
    int tid = threadIdx.x;
    for (int i = tid; i < 128 * 16; i += 256) Ws[i] = W[i];
    int node0 = blockIdx.x * 16;
    for (int i = tid; i < 16 * 128; i += 256) {
        int r = i >> 7, c = i & 127;
        int gr = node0 + r;
        Hs[r][c] = (gr < N_NODES) ? g_out1[(size_t)gr * 128 + c] : 0.f;
    }
    __syncthreads();
    int ln = tid >> 4;
    int oc = tid & 15;
    float acc = 0.f;
    #pragma unroll
    for (int k = 0; k < 128; k++) acc += Hs[ln][k] * Ws[k * 16 + oc];
    int gr = node0 + ln;
    if (gr < N_NODES) g_h3[(size_t)gr * 16 + oc] = acc;
}

// ---------------------------------------------------------------------------
// Attention dots, layer 2 (1 head): thread per node
// ---------------------------------------------------------------------------
__global__ void attdot2_kernel(const float* __restrict__ att_src,
                               const float* __restrict__ att_dst)
{
    int n = blockIdx.x * blockDim.x + threadIdx.x;
    if (n >= N_NODES) return;
    const float* hp = g_h3 + (size_t)n * OUT_C;
    float ss = 0.f, dd = 0.f;
    #pragma unroll
    for (int c = 0; c < OUT_C; c++) {
        float v = hp[c];
        ss += v * att_src[c];
        dd += v * att_dst[c];
    }
    g_asrc2[n] = ss;
    g_adst2[n] = dd;
}

// ---------------------------------------------------------------------------
// Edge pass: denominator, layer 2. Thread per edge.
// ---------------------------------------------------------------------------
__global__ void edge_denom2_kernel(const int* __restrict__ ei)
{
    int e = blockIdx.x * blockDim.x + threadIdx.x;
    if (e >= E_TOT) return;
    int s, d;
    if (e < N_EDGES) { s = ei[e]; d = ei[N_EDGES + e]; }
    else             { s = d = e - N_EDGES; }
    float a = g_asrc2[s] + g_adst2[d];
    a = (a > 0.f) ? a : NEG_SLOPE * a;
    atomicAdd(&g_denom2[d], __expf(a));
}

// ---------------------------------------------------------------------------
// Edge pass: weighted scatter, layer 2 into d_out. Thread per (edge, quad).
// ---------------------------------------------------------------------------
__global__ void edge_scatter2_kernel(const int* __restrict__ ei, float* __restrict__ out)
{
    long long idx = (long long)blockIdx.x * blockDim.x + threadIdx.x;
    if (idx >= (long long)E_TOT * 4) return;
    int e = (int)(idx >> 2);
    int q = (int)(idx & 3);
    int s, d;
    if (e < N_EDGES) { s = ei[e]; d = ei[N_EDGES + e]; }
    else             { s = d = e - N_EDGES; }
    float a = g_asrc2[s] + g_adst2[d];
    a = (a > 0.f) ? a : NEG_SLOPE * a;
    float w = __expf(a) / g_denom2[d];
    float4 hv = *reinterpret_cast<const float4*>(g_h3 + (size_t)s * OUT_C + q * 4);
    float4 m = make_float4(hv.x * w, hv.y * w, hv.z * w, hv.w * w);
    atomicAdd(reinterpret_cast<float4*>(out + (size_t)d * OUT_C + q * 4), m);
}

// ---------------------------------------------------------------------------
// Final bias add (bias2 is zeros in this dataset, but keep it general)
// ---------------------------------------------------------------------------
__global__ void bias2_kernel(float* __restrict__ out, const float* __restrict__ bias2)
{
    int idx = blockIdx.x * blockDim.x + threadIdx.x;
    if (idx >= N_NODES * OUT_C) return;
    out[idx] += bias2[idx & (OUT_C - 1)];
}

// ---------------------------------------------------------------------------
extern "C" void kernel_launch(void* const* d_in, const int* in_sizes, int n_in,
                              void* d_out, int out_size)
{
    const float* x        = (const float*)d_in[0];
    const int*   ei       = (const int*)  d_in[1];
    const float* W1       = (const float*)d_in[2];
    const float* att_src1 = (const float*)d_in[3];
    const float* att_dst1 = (const float*)d_in[4];
    const float* bias1    = (const float*)d_in[5];
    const float* W2       = (const float*)d_in[6];
    const float* att_src2 = (const float*)d_in[7];
    const float* att_dst2 = (const float*)d_in[8];
    const float* bias2    = (const float*)d_in[9];
    float* out = (float*)d_out;

    (void)in_sizes; (void)n_in; (void)out_size;

    const int T = 256;

    // init scratch + output accumulators
    zero_scratch_kernel<<<(N_NODES * HID_C + T - 1) / T, T>>>();
    zero_out_kernel<<<(N_NODES * OUT_C + T - 1) / T, T>>>(out, N_NODES * OUT_C);

    // layer 1
    float* h1 = nullptr;  // use symbols directly inside kernels; gemm1 needs pointer
    cudaGetSymbolAddress((void**)&h1, g_h1);
    gemm1_kernel<<<(N_NODES + 127) / 128, 256>>>(x, W1, h1);
    attdot1_kernel<<<(N_NODES * HEADS + T - 1) / T, T>>>(att_src1, att_dst1);

    long long nd1 = (long long)E_TOT * HEADS;
    edge_denom1_kernel<<<(int)((nd1 + T - 1) / T), T>>>(ei);

    long long sc1_threads = (long long)E_TOT * 32;
    edge_scatter1_kernel<<<(int)((sc1_threads + T - 1) / T), T>>>(ei);

    relu_bias1_kernel<<<(N_NODES * HID_C + T - 1) / T, T>>>(bias1);

    // layer 2
    gemm2_kernel<<<(N_NODES + 15) / 16, 256>>>(W2);
    attdot2_kernel<<<(N_NODES + T - 1) / T, T>>>(att_src2, att_dst2);
    edge_denom2_kernel<<<(E_TOT + T - 1) / T, T>>>(ei);

    long long sc2_threads = (long long)E_TOT * 4;
    edge_scatter2_kernel<<<(int)((sc2_threads + T - 1) / T), T>>>(ei, out);

    bias2_kernel<<<(N_NODES * OUT_C + T - 1) / T, T>>>(out, bias2);
}

// round 7
// speedup vs baseline: 1.0007x; 1.0007x over previous
#include <cuda_runtime.h>
#include <cuda_bf16.h>

// Problem constants
#define N_NODES  50000
#define N_EDGES  1600000
#define E_TOT    (N_EDGES + N_NODES)   // with self loops
#define IN_C     256
#define HID_C    128
#define OUT_C    16
#define HEADS    8
#define C1       16                    // HID_C / HEADS
#define NEG_SLOPE 0.2f

// ---------------------------------------------------------------------------
// Scratch (device globals; allocation inside kernel_launch is forbidden)
// ---------------------------------------------------------------------------
__device__ float g_h1[(size_t)N_NODES * HID_C];     // layer1 transformed features
__device__ float g_asrc1[(size_t)N_NODES * HEADS];
__device__ float g_adst1[(size_t)N_NODES * HEADS];
__device__ float g_denom1[(size_t)N_NODES * HEADS];
__device__ float g_out1[(size_t)N_NODES * HID_C];   // layer1 aggregation -> relu -> h2
__device__ float g_h3[(size_t)N_NODES * OUT_C];     // layer2 transformed features
__device__ float g_asrc2[N_NODES];
__device__ float g_adst2[N_NODES];
__device__ float g_denom2[N_NODES];

// ---------------------------------------------------------------------------
// Zero-init: g_out1 (6.4M), g_denom1 (400K), g_denom2 (50K)
// ---------------------------------------------------------------------------
__global__ void zero_scratch_kernel() {
    int idx = blockIdx.x * blockDim.x + threadIdx.x;
    if (idx < N_NODES * HID_C)  g_out1[idx]   = 0.f;
    if (idx < N_NODES * HEADS)  g_denom1[idx] = 0.f;
    if (idx < N_NODES)          g_denom2[idx] = 0.f;
}

__global__ void zero_out_kernel(float* p, int n) {
    int idx = blockIdx.x * blockDim.x + threadIdx.x;
    if (idx < n) p[idx] = 0.f;
}

// ---------------------------------------------------------------------------
// GEMM1: C[50000,128] = A[50000,256] @ B[256,128]
// BM=128 BN=128 BK=8, 256 threads, 8x8 per thread
// ---------------------------------------------------------------------------
__global__ __launch_bounds__(256) void gemm1_kernel(
    const float* __restrict__ A, const float* __restrict__ B, float* __restrict__ C)
{
    __shared__ float As[8][128];
    __shared__ float Bs[8][128];

    const int tid = threadIdx.x;
    const int tx = tid % 16;        // col group
    const int ty = tid / 16;        // row group
    const int row0 = blockIdx.x * 128;

    const int aRow = tid >> 1;          // 0..127
    const int aCol = (tid & 1) * 4;     // 0 or 4
    const int bRow = tid >> 5;          // 0..7
    const int bCol = (tid & 31) * 4;    // 0..124

    float acc[8][8];
    #pragma unroll
    for (int i = 0; i < 8; i++)
        #pragma unroll
        for (int j = 0; j < 8; j++) acc[i][j] = 0.f;

    for (int kt = 0; kt < IN_C; kt += 8) {
        int gr = row0 + aRow;
        float4 av = (gr < N_NODES)
            ? *reinterpret_cast<const float4*>(A + (size_t)gr * IN_C + kt + aCol)
            : make_float4(0.f, 0.f, 0.f, 0.f);
        As[aCol + 0][aRow] = av.x;
        As[aCol + 1][aRow] = av.y;
        As[aCol + 2][aRow] = av.z;
        As[aCol + 3][aRow] = av.w;

        float4 bv = *reinterpret_cast<const float4*>(B + (size_t)(kt + bRow) * 128 + bCol);
        *reinterpret_cast<float4*>(&Bs[bRow][bCol]) = bv;

        __syncthreads();

        #pragma unroll
        for (int k = 0; k < 8; k++) {
            float ra[8], rb[8];
            #pragma unroll
            for (int i = 0; i < 8; i++) ra[i] = As[k][ty * 8 + i];
            #pragma unroll
            for (int j = 0; j < 8; j++) rb[j] = Bs[k][tx * 8 + j];
            #pragma unroll
            for (int i = 0; i < 8; i++)
                #pragma unroll
                for (int j = 0; j < 8; j++) acc[i][j] += ra[i] * rb[j];
        }
        __syncthreads();
    }

    #pragma unroll
    for (int i = 0; i < 8; i++) {
        int r = row0 + ty * 8 + i;
        if (r < N_NODES) {
            #pragma unroll
            for (int j = 0; j < 8; j += 4) {
                float4 v = make_float4(acc[i][j], acc[i][j+1], acc[i][j+2], acc[i][j+3]);
                *reinterpret_cast<float4*>(C + (size_t)r * 128 + tx * 8 + j) = v;
            }
        }
    }
}

// ---------------------------------------------------------------------------
// Attention dot products, layer 1: one thread per (node, head)
// ---------------------------------------------------------------------------
__global__ void attdot1_kernel(const float* __restrict__ att_src,
                               const float* __restrict__ att_dst)
{
    int idx = blockIdx.x * blockDim.x + threadIdx.x;  // n*8 + head
    if (idx >= N_NODES * HEADS) return;
    int head = idx & 7;
    const float* hp = g_h1 + (size_t)(idx >> 3) * HID_C + head * C1;
    const float* sp = att_src + head * C1;
    const float* dp = att_dst + head * C1;
    float ss = 0.f, dd = 0.f;
    #pragma unroll
    for (int c = 0; c < C1; c++) {
        float v = hp[c];
        ss += v * sp[c];
        dd += v * dp[c];
    }
    g_asrc1[idx] = ss;
    g_adst1[idx] = dd;
}

// ---------------------------------------------------------------------------
// Edge pass: softmax denominator, layer 1. Thread per (edge, head).
// NOTE: segment-max subtraction skipped — mathematically identical softmax,
// logits are small (|alpha| < ~5) so exp is safe in fp32.
// ---------------------------------------------------------------------------
__global__ void edge_denom1_kernel(const int* __restrict__ ei)
{
    long long idx = (long long)blockIdx.x * blockDim.x + threadIdx.x;
    if (idx >= (long long)E_TOT * HEADS) return;
    int e = (int)(idx >> 3);
    int h = (int)(idx & 7);
    int s, d;
    if (e < N_EDGES) { s = ei[e]; d = ei[N_EDGES + e]; }
    else             { s = d = e - N_EDGES; }
    float a = g_asrc1[s * HEADS + h] + g_adst1[d * HEADS + h];
    a = (a > 0.f) ? a : NEG_SLOPE * a;
    atomicAdd(&g_denom1[d * HEADS + h], __expf(a));
}

// ---------------------------------------------------------------------------
// Edge pass: weighted scatter, layer 1. One warp per edge; lane handles 4 ch.
// ---------------------------------------------------------------------------
__global__ void edge_scatter1_kernel(const int* __restrict__ ei)
{
    int warp = (blockIdx.x * blockDim.x + threadIdx.x) >> 5;
    int lane = threadIdx.x & 31;
    if (warp >= E_TOT) return;
    int s, d;
    if (warp < N_EDGES) { s = ei[warp]; d = ei[N_EDGES + warp]; }
    else                { s = d = warp - N_EDGES; }
    int head = lane >> 2;
    float a = g_asrc1[s * HEADS + head] + g_adst1[d * HEADS + head];
    a = (a > 0.f) ? a : NEG_SLOPE * a;
    float w = __expf(a) / g_denom1[d * HEADS + head];

    float4 hv = *reinterpret_cast<const float4*>(g_h1 + (size_t)s * HID_C + lane * 4);
    float4 m = make_float4(hv.x * w, hv.y * w, hv.z * w, hv.w * w);
    atomicAdd(reinterpret_cast<float4*>(g_out1 + (size_t)d * HID_C + lane * 4), m);
}

// ---------------------------------------------------------------------------
// Epilogue layer 1: bias + relu (in place; g_out1 becomes h2)
// ---------------------------------------------------------------------------
__global__ void relu_bias1_kernel(const float* __restrict__ bias1)
{
    int idx = blockIdx.x * blockDim.x + threadIdx.x;
    if (idx >= N_NODES * HID_C) return;
    float v = g_out1[idx] + bias1[idx & (HID_C - 1)];
    g_out1[idx] = (v > 0.f) ? v : 0.f;
}

// ---------------------------------------------------------------------------
// GEMM2: C[50000,16] = h2[50000,128] @ W2[128,16]
// block = 256 threads = 16 nodes x 16 outputs
// ---------------------------------------------------------------------------
__global__ __launch_bounds__(256) void gemm2_kernel(const float* __restrict__ W)
{
    __shared__ float Ws[128 * 16];
    __shared__ float Hs[16][128];
    int tid = threadIdx.x;
    for (int i = tid; i < 128 * 16; i += 256) Ws[i] = W[i];
    int node0 = blockIdx.x * 16;
    for (int i = tid; i < 16 * 128; i += 256) {
        int r = i >> 7, c = i & 127;
        int gr = node0 + r;
        Hs[r][c] = (gr < N_NODES) ? g_out1[(size_t)gr * 128 + c] : 0.f;
    }
    __syncthreads();
    int ln = tid >> 4;
    int oc = tid & 15;
    float acc = 0.f;
    #pragma unroll
    for (int k = 0; k < 128; k++) acc += Hs[ln][k] * Ws[k * 16 + oc];
    int gr = node0 + ln;
    if (gr < N_NODES) g_h3[(size_t)gr * 16 + oc] = acc;
}

// ---------------------------------------------------------------------------
// Attention dots, layer 2 (1 head): thread per node
// ---------------------------------------------------------------------------
__global__ void attdot2_kernel(const float* __restrict__ att_src,
                               const float* __restrict__ att_dst)
{
    int n = blockIdx.x * blockDim.x + threadIdx.x;
    if (n >= N_NODES) return;
    const float* hp = g_h3 + (size_t)n * OUT_C;
    float ss = 0.f, dd = 0.f;
    #pragma unroll
    for (int c = 0; c < OUT_C; c++) {
        float v = hp[c];
        ss += v * att_src[c];
        dd += v * att_dst[c];
    }
    g_asrc2[n] = ss;
    g_adst2[n] = dd;
}

// ---------------------------------------------------------------------------
// Edge pass: denominator, layer 2. Thread per edge.
// ---------------------------------------------------------------------------
__global__ void edge_denom2_kernel(const int* __restrict__ ei)
{
    int e = blockIdx.x * blockDim.x + threadIdx.x;
    if (e >= E_TOT) return;
    int s, d;
    if (e < N_EDGES) { s = ei[e]; d = ei[N_EDGES + e]; }
    else             { s = d = e - N_EDGES; }
    float a = g_asrc2[s] + g_adst2[d];
    a = (a > 0.f) ? a : NEG_SLOPE * a;
    atomicAdd(&g_denom2[d], __expf(a));
}

// ---------------------------------------------------------------------------
// Edge pass: weighted scatter, layer 2 into d_out. Thread per (edge, quad).
// ---------------------------------------------------------------------------
__global__ void edge_scatter2_kernel(const int* __restrict__ ei, float* __restrict__ out)
{
    long long idx = (long long)blockIdx.x * blockDim.x + threadIdx.x;
    if (idx >= (long long)E_TOT * 4) return;
    int e = (int)(idx >> 2);
    int q = (int)(idx & 3);
    int s, d;
    if (e < N_EDGES) { s = ei[e]; d = ei[N_EDGES + e]; }
    else             { s = d = e - N_EDGES; }
    float a = g_asrc2[s] + g_adst2[d];
    a = (a > 0.f) ? a : NEG_SLOPE * a;
    float w = __expf(a) / g_denom2[d];
    float4 hv = *reinterpret_cast<const float4*>(g_h3 + (size_t)s * OUT_C + q * 4);
    float4 m = make_float4(hv.x * w, hv.y * w, hv.z * w, hv.w * w);
    atomicAdd(reinterpret_cast<float4*>(out + (size_t)d * OUT_C + q * 4), m);
}

// ---------------------------------------------------------------------------
// Final bias add (bias2 is zeros in this dataset, but keep it general)
// ---------------------------------------------------------------------------
__global__ void bias2_kernel(float* __restrict__ out, const float* __restrict__ bias2)
{
    int idx = blockIdx.x * blockDim.x + threadIdx.x;
    if (idx >= N_NODES * OUT_C) return;
    out[idx] += bias2[idx & (OUT_C - 1)];
}

// ---------------------------------------------------------------------------
extern "C" void kernel_launch(void* const* d_in, const int* in_sizes, int n_in,
                              void* d_out, int out_size)
{
    const float* x        = (const float*)d_in[0];
    const int*   ei       = (const int*)  d_in[1];
    const float* W1       = (const float*)d_in[2];
    const float* att_src1 = (const float*)d_in[3];
    const float* att_dst1 = (const float*)d_in[4];
    const float* bias1    = (const float*)d_in[5];
    const float* W2       = (const float*)d_in[6];
    const float* att_src2 = (const float*)d_in[7];
    const float* att_dst2 = (const float*)d_in[8];
    const float* bias2    = (const float*)d_in[9];
    float* out = (float*)d_out;

    (void)in_sizes; (void)n_in; (void)out_size;

    const int T = 256;

    // init scratch + output accumulators
    zero_scratch_kernel<<<(N_NODES * HID_C + T - 1) / T, T>>>();
    zero_out_kernel<<<(N_NODES * OUT_C + T - 1) / T, T>>>(out, N_NODES * OUT_C);

    // layer 1
    float* h1 = nullptr;  // use symbols directly inside kernels; gemm1 needs pointer
    cudaGetSymbolAddress((void**)&h1, g_h1);
    gemm1_kernel<<<(N_NODES + 127) / 128, 256>>>(x, W1, h1);
    attdot1_kernel<<<(N_NODES * HEADS + T - 1) / T, T>>>(att_src1, att_dst1);

    long long nd1 = (long long)E_TOT * HEADS;
    edge_denom1_kernel<<<(int)((nd1 + T - 1) / T), T>>>(ei);

    long long sc1_threads = (long long)E_TOT * 32;
    edge_scatter1_kernel<<<(int)((sc1_threads + T - 1) / T), T>>>(ei);

    relu_bias1_kernel<<<(N_NODES * HID_C + T - 1) / T, T>>>(bias1);

    // layer 2
    gemm2_kernel<<<(N_NODES + 15) / 16, 256>>>(W2);
    attdot2_kernel<<<(N_NODES + T - 1) / T, T>>>(att_src2, att_dst2);
    edge_denom2_kernel<<<(E_TOT + T - 1) / T, T>>>(ei);

    long long sc2_threads = (long long)E_TOT * 4;
    edge_scatter2_kernel<<<(int)((sc2_threads + T - 1) / T), T>>>(ei, out);

    bias2_kernel<<<(N_NODES * OUT_C + T - 1) / T, T>>>(out, bias2);
}